// round 12
// baseline (speedup 1.0000x reference)
#include <cuda_runtime.h>
#include <cuda_bf16.h>
#include <cstdint>

#define N_NODES 100000
#define NFEAT   256
#define NHID    256
#define NCLASS  64
#define KDIM    256

// ---------------- scratch (device globals; no runtime allocation) ----------------
__device__ __align__(128) float         g_S[(size_t)N_NODES * NHID];     // fp32 GEMM out / SpMM in
__device__ __align__(128) __nv_bfloat16 g_xh[(size_t)N_NODES * NFEAT];
__device__ __align__(128) __nv_bfloat16 g_xl[(size_t)N_NODES * NFEAT];
__device__ __align__(128) __nv_bfloat16 g_hh[(size_t)N_NODES * NHID];
__device__ __align__(128) __nv_bfloat16 g_hl[(size_t)N_NODES * NHID];
__device__ __align__(128) __nv_bfloat16 g_w1t_h[KDIM * NHID], g_w1t_l[KDIM * NHID]; // W1^T [N,K]
__device__ __align__(128) __nv_bfloat16 g_w2t_h[KDIM * NHID], g_w2t_l[KDIM * NHID]; // W2^T
__device__ __align__(128) __nv_bfloat16 g_wht_h[128 * KDIM],  g_wht_l[128 * KDIM];  // [WL1|WL2]^T
__device__ float g_headb[2 * NCLASS];
__device__ int   g_row_ptr[N_NODES + 1];

// ---------------- small PTX helpers ----------------
__device__ __forceinline__ void cp16(uint32_t s, const __nv_bfloat16* g, bool v) {
    int sz = v ? 16 : 0;
    asm volatile("cp.async.cg.shared.global [%0], [%1], 16, %2;"
                 :: "r"(s), "l"(__cvta_generic_to_global(g)), "r"(sz));
}
#define CP_COMMIT() asm volatile("cp.async.commit_group;" ::: "memory")

__device__ __forceinline__ void ldsm4(uint32_t* r, uint32_t a) {
    asm volatile("ldmatrix.sync.aligned.m8n8.x4.shared.b16 {%0,%1,%2,%3}, [%4];"
                 : "=r"(r[0]), "=r"(r[1]), "=r"(r[2]), "=r"(r[3]) : "r"(a));
}
__device__ __forceinline__ void mma16816(float* c, const uint32_t* a, const uint32_t* b) {
    asm volatile("mma.sync.aligned.m16n8k16.row.col.f32.bf16.bf16.f32 "
                 "{%0,%1,%2,%3}, {%4,%5,%6,%7}, {%8,%9}, {%0,%1,%2,%3};"
                 : "+f"(c[0]), "+f"(c[1]), "+f"(c[2]), "+f"(c[3])
                 : "r"(a[0]), "r"(a[1]), "r"(a[2]), "r"(a[3]), "r"(b[0]), "r"(b[1]));
}

// ---------------- CSR row_ptr from sorted edge_dst ----------------
__global__ void build_row_ptr_kernel(const int* __restrict__ dst, int n_edges) {
    int i = blockIdx.x * blockDim.x + threadIdx.x;
    if (i > N_NODES) return;
    int lo = 0, hi = n_edges;
    while (lo < hi) {
        int mid = (lo + hi) >> 1;
        if (dst[mid] < i) lo = mid + 1; else hi = mid;
    }
    g_row_ptr[i] = lo;
}

// ---------------- weight prep: transpose + bf16 split ----------------
__device__ __forceinline__ void split_store(__nv_bfloat16* ph, __nv_bfloat16* pl, float v) {
    __nv_bfloat16 hi = __float2bfloat16(v);
    *ph = hi;
    *pl = __float2bfloat16(v - __bfloat162float(hi));
}
__global__ void prep_w_kernel(const float* __restrict__ W1, const float* __restrict__ W2,
                              const float* __restrict__ WL1, const float* __restrict__ WL2,
                              const float* __restrict__ bL1, const float* __restrict__ bL2) {
    int i = blockIdx.x * blockDim.x + threadIdx.x;
    if (i < KDIM * NHID) {
        int n = i >> 8, k = i & 255;
        split_store(&g_w1t_h[i], &g_w1t_l[i], W1[k * NHID + n]);
        split_store(&g_w2t_h[i], &g_w2t_l[i], W2[k * NHID + n]);
    }
    if (i < 128 * KDIM) {
        int n = i >> 8, k = i & 255;
        float v = (n < NCLASS) ? WL1[k * NCLASS + n] : WL2[k * NCLASS + (n - NCLASS)];
        split_store(&g_wht_h[i], &g_wht_l[i], v);
    }
    if (i < 2 * NCLASS)
        g_headb[i] = (i < NCLASS) ? bL1[i] : bL2[i - NCLASS];
}

// ---------------- x -> bf16 hi/lo ----------------
__global__ void convert_x_kernel(const float* __restrict__ x) {
    int i = blockIdx.x * blockDim.x + threadIdx.x;
    if (i >= N_NODES * NFEAT) return;
    split_store(&g_xh[i], &g_xl[i], x[i]);
}

// ---------------- mma.sync split-bf16 GEMM (CTA 128x128, KC=32, single stage, 4+ CTA/SM) ----------------
// C = (Ah+Al) @ (Bh+Bl)^T via AhBh + AhBl + AlBh, fp32 accum.
// A: [M,256] bf16 row-major; B: [Nrows,256] bf16 row-major (= W^T, K-major).
// Single 40KB stage; latency hidden by inter-CTA interleaving (4-5 CTAs/SM).
constexpr int KC     = 32;
constexpr int ROWB   = 80;             // (32+8) halves * 2B; 8-row ldsm conflict-free
constexpr int TILEB  = 128 * ROWB;     // 10240
constexpr int STAGEB = 4 * TILEB;      // 40960  (tiles: Ah, Al, Bh, Bl)
constexpr int GEMM_SMEM = STAGEB;      // 40960  -> up to 5 CTAs/SM by smem

template <bool HEAD>
__global__ void __launch_bounds__(256, 4) gemm_mma_kernel(
    const __nv_bfloat16* __restrict__ Ah, const __nv_bfloat16* __restrict__ Al,
    const __nv_bfloat16* __restrict__ Bh, const __nv_bfloat16* __restrict__ Bl,
    float* __restrict__ out, int M, int ldC)
{
    extern __shared__ __align__(128) char smem[];
    const int tid = threadIdx.x, lane = tid & 31, wid = tid >> 5;
    const int wm = wid >> 2, wn = wid & 3;            // 2(M) x 4(N) warps, warp tile 64x32
    const int m0 = blockIdx.y * 128;
    const int n0 = blockIdx.x * 128;
    const __nv_bfloat16* BhO = Bh + (size_t)n0 * KDIM;
    const __nv_bfloat16* BlO = Bl + (size_t)n0 * KDIM;
    uint32_t sb = (uint32_t)__cvta_generic_to_shared(smem);

    float acc[4][4][4];
#pragma unroll
    for (int a = 0; a < 4; a++)
#pragma unroll
        for (int b = 0; b < 4; b++)
#pragma unroll
            for (int c = 0; c < 4; c++) acc[a][b][c] = 0.f;

    // stage loader: 4 tiles x 128 rows x 2 chunks(16B) = 2048 cp.async (wait, 4 chunks? KC=32 -> 64B/row = 4x16B)
    auto load_stage = [&](int kc) {
        for (int i = tid; i < 2048; i += 256) {
            int t = i >> 9, rc = i & 511, r = rc >> 2, ch = rc & 3;
            const __nv_bfloat16* src;
            bool v = true;
            if (t == 0)      { src = Ah  + (size_t)(m0 + r) * KDIM + kc + ch * 8; v = (m0 + r) < M; }
            else if (t == 1) { src = Al  + (size_t)(m0 + r) * KDIM + kc + ch * 8; v = (m0 + r) < M; }
            else if (t == 2) { src = BhO + (size_t)r * KDIM + kc + ch * 8; }
            else             { src = BlO + (size_t)r * KDIM + kc + ch * 8; }
            cp16(sb + t * TILEB + r * ROWB + ch * 16, src, v);
        }
    };

    const int ar  = lane & 15;
    const int acx = ((lane >> 4) & 1) * 8;
    const int br  = ((lane >> 4) << 3) + (lane & 7);
    const int bc  = ((lane >> 3) & 1) * 8;

    auto compute = [&]() {
        uint32_t aH = sb;
        uint32_t aL = sb + TILEB;
        uint32_t bH = sb + 2 * TILEB;
        uint32_t bL = sb + 3 * TILEB;
#pragma unroll
        for (int k16 = 0; k16 < KC / 16; k16++) {
            uint32_t ah[4][4], al[4][4], bh[4][2], bl[4][2];
#pragma unroll
            for (int mf = 0; mf < 4; mf++) {
                uint32_t off = (uint32_t)((wm * 64 + mf * 16 + ar) * ROWB + (acx + k16 * 16) * 2);
                ldsm4(ah[mf], aH + off);
                ldsm4(al[mf], aL + off);
            }
#pragma unroll
            for (int np = 0; np < 2; np++) {
                uint32_t off = (uint32_t)((wn * 32 + np * 16 + br) * ROWB + (bc + k16 * 16) * 2);
                uint32_t t[4];
                ldsm4(t, bH + off);
                bh[np*2][0] = t[0]; bh[np*2][1] = t[1]; bh[np*2+1][0] = t[2]; bh[np*2+1][1] = t[3];
                ldsm4(t, bL + off);
                bl[np*2][0] = t[0]; bl[np*2][1] = t[1]; bl[np*2+1][0] = t[2]; bl[np*2+1][1] = t[3];
            }
#pragma unroll
            for (int mf = 0; mf < 4; mf++)
#pragma unroll
                for (int nf = 0; nf < 4; nf++) {
                    mma16816(acc[mf][nf], ah[mf], bh[nf]);
                    mma16816(acc[mf][nf], ah[mf], bl[nf]);
                    mma16816(acc[mf][nf], al[mf], bh[nf]);
                }
        }
    };

    constexpr int NIT = KDIM / KC;   // 8
#pragma unroll
    for (int it = 0; it < NIT; it++) {
        load_stage(it * KC);
        CP_COMMIT();
        asm volatile("cp.async.wait_group 0;" ::: "memory");
        __syncthreads();
        compute();
        __syncthreads();
    }

    // ---- epilogue ----
#pragma unroll
    for (int mf = 0; mf < 4; mf++) {
        int rbase = m0 + wm * 64 + mf * 16 + (lane >> 2);
#pragma unroll
        for (int nf = 0; nf < 4; nf++) {
            int col = (HEAD ? 0 : n0) + wn * 32 + nf * 8 + (lane & 3) * 2;
#pragma unroll
            for (int h = 0; h < 2; h++) {
                int row = rbase + h * 8;
                if (row >= M) continue;
                float2 v = make_float2(acc[mf][nf][h * 2], acc[mf][nf][h * 2 + 1]);
                if (!HEAD) {
                    *(float2*)(out + (size_t)row * ldC + col) = v;
                } else {
                    v.x += g_headb[col]; v.y += g_headb[col + 1];
                    float* dst = (col < NCLASS)
                        ? out + (size_t)row * NCLASS + col
                        : out + (size_t)N_NODES * NCLASS + (size_t)row * NCLASS + (col - NCLASS);
                    *(float2*)dst = v;
                }
            }
        }
    }
}

// ---------------- SpMM half-pass + bias + relu -> bf16 hi/lo split ----------------
// Processes 128 feature columns per pass (working set 51MB -> L2-resident).
struct __align__(8) bf16x4 { __nv_bfloat162 a, b; };
__device__ __forceinline__ void emit4(__nv_bfloat16* Hh, __nv_bfloat16* Hl, size_t idx,
                                      float4 acc, float4 bia) {
    float v0 = fmaxf(acc.x + bia.x, 0.f), v1 = fmaxf(acc.y + bia.y, 0.f);
    float v2 = fmaxf(acc.z + bia.z, 0.f), v3 = fmaxf(acc.w + bia.w, 0.f);
    __nv_bfloat16 h0 = __float2bfloat16(v0), h1 = __float2bfloat16(v1);
    __nv_bfloat16 h2 = __float2bfloat16(v2), h3 = __float2bfloat16(v3);
    bf16x4 hv; hv.a = __nv_bfloat162(h0, h1); hv.b = __nv_bfloat162(h2, h3);
    *(bf16x4*)(Hh + idx) = hv;
    bf16x4 lv;
    lv.a = __nv_bfloat162(__float2bfloat16(v0 - __bfloat162float(h0)),
                          __float2bfloat16(v1 - __bfloat162float(h1)));
    lv.b = __nv_bfloat162(__float2bfloat16(v2 - __bfloat162float(h2)),
                          __float2bfloat16(v3 - __bfloat162float(h3)));
    *(bf16x4*)(Hl + idx) = lv;
}

__device__ __forceinline__ void fma4(float4& acc, float s, const float4& v) {
    acc.x += s * v.x; acc.y += s * v.y; acc.z += s * v.z; acc.w += s * v.w;
}

__global__ void __launch_bounds__(256) spmm_half_kernel(
    const float* __restrict__ S, const int* __restrict__ src,
    const float* __restrict__ w, const float* __restrict__ bias,
    __nv_bfloat16* __restrict__ Hh, __nv_bfloat16* __restrict__ Hl, int colOff)
{
    int node = (blockIdx.x * blockDim.x + threadIdx.x) >> 5;
    if (node >= N_NODES) return;
    int lane = threadIdx.x & 31;
    int e0 = g_row_ptr[node], e1 = g_row_ptr[node + 1];
    const float* Sc = S + colOff + lane * 4;

    float4 acc = make_float4(0.f, 0.f, 0.f, 0.f);
    int e = e0;
    for (; e + 4 <= e1; e += 4) {
        int   s0 = __ldg(src + e),     s1 = __ldg(src + e + 1);
        int   s2 = __ldg(src + e + 2), s3 = __ldg(src + e + 3);
        float w0 = __ldg(w + e),     w1 = __ldg(w + e + 1);
        float w2 = __ldg(w + e + 2), w3 = __ldg(w + e + 3);
        float4 a0 = __ldg((const float4*)(Sc + (size_t)s0 * NHID));
        float4 a1 = __ldg((const float4*)(Sc + (size_t)s1 * NHID));
        float4 a2 = __ldg((const float4*)(Sc + (size_t)s2 * NHID));
        float4 a3 = __ldg((const float4*)(Sc + (size_t)s3 * NHID));
        fma4(acc, w0, a0); fma4(acc, w1, a1); fma4(acc, w2, a2); fma4(acc, w3, a3);
    }
    for (; e < e1; e++) {
        int   s  = __ldg(src + e);
        float sw = __ldg(w + e);
        float4 a = __ldg((const float4*)(Sc + (size_t)s * NHID));
        fma4(acc, sw, a);
    }

    float4 bia = *(const float4*)(bias + colOff + lane * 4);
    emit4(Hh, Hl, (size_t)node * NHID + colOff + lane * 4, acc, bia);
}

// ---------------- launch ----------------
extern "C" void kernel_launch(void* const* d_in, const int* in_sizes, int n_in,
                              void* d_out, int out_size) {
    const float* x   = (const float*)d_in[0];
    const int*   es  = (const int*)  d_in[1];
    const int*   ed  = (const int*)  d_in[2];
    const float* ew  = (const float*)d_in[3];
    const float* W1  = (const float*)d_in[4];
    const float* b1  = (const float*)d_in[5];
    const float* W2  = (const float*)d_in[6];
    const float* b2  = (const float*)d_in[7];
    const float* WL1 = (const float*)d_in[8];
    const float* bL1 = (const float*)d_in[9];
    const float* WL2 = (const float*)d_in[10];
    const float* bL2 = (const float*)d_in[11];
    int n_edges = in_sizes[1];

    float *S; __nv_bfloat16 *xh, *xl, *hh, *hl, *w1h, *w1l, *w2h, *w2l, *whh, *whl;
    cudaGetSymbolAddress((void**)&S,   g_S);
    cudaGetSymbolAddress((void**)&xh,  g_xh);    cudaGetSymbolAddress((void**)&xl,  g_xl);
    cudaGetSymbolAddress((void**)&hh,  g_hh);    cudaGetSymbolAddress((void**)&hl,  g_hl);
    cudaGetSymbolAddress((void**)&w1h, g_w1t_h); cudaGetSymbolAddress((void**)&w1l, g_w1t_l);
    cudaGetSymbolAddress((void**)&w2h, g_w2t_h); cudaGetSymbolAddress((void**)&w2l, g_w2t_l);
    cudaGetSymbolAddress((void**)&whh, g_wht_h); cudaGetSymbolAddress((void**)&whl, g_wht_l);

    cudaFuncSetAttribute(gemm_mma_kernel<false>,
                         cudaFuncAttributeMaxDynamicSharedMemorySize, GEMM_SMEM);
    cudaFuncSetAttribute(gemm_mma_kernel<true>,
                         cudaFuncAttributeMaxDynamicSharedMemorySize, GEMM_SMEM);

    const int MTILES = (N_NODES + 127) / 128;   // 782
    const int spmm_blocks = (N_NODES + 7) / 8;  // 8 warps/block

    build_row_ptr_kernel<<<(N_NODES + 256) / 256, 256>>>(ed, n_edges);
    prep_w_kernel<<<(KDIM * NHID + 255) / 256, 256>>>(W1, W2, WL1, WL2, bL1, bL2);
    convert_x_kernel<<<(N_NODES * NFEAT + 255) / 256, 256>>>(x);

    // layer 1
    gemm_mma_kernel<false><<<dim3(2, MTILES), 256, GEMM_SMEM>>>(xh, xl, w1h, w1l, S, N_NODES, NHID);
    spmm_half_kernel<<<spmm_blocks, 256>>>(S, es, ew, b1, hh, hl, 0);
    spmm_half_kernel<<<spmm_blocks, 256>>>(S, es, ew, b1, hh, hl, 128);
    // layer 2
    gemm_mma_kernel<false><<<dim3(2, MTILES), 256, GEMM_SMEM>>>(hh, hl, w2h, w2l, S, N_NODES, NHID);
    spmm_half_kernel<<<spmm_blocks, 256>>>(S, es, ew, b2, hh, hl, 0);
    spmm_half_kernel<<<spmm_blocks, 256>>>(S, es, ew, b2, hh, hl, 128);
    // twin heads
    gemm_mma_kernel<true><<<dim3(1, MTILES), 256, GEMM_SMEM>>>(hh, hl, whh, whl, (float*)d_out, N_NODES, 128);
}

// round 14
// speedup vs baseline: 2.2009x; 2.2009x over previous
#include <cuda_runtime.h>
#include <cuda_bf16.h>
#include <cstdint>

#define N_NODES 100000
#define NFEAT   256
#define NHID    256
#define NCLASS  64
#define KDIM    256

// ---------------- scratch (device globals; no runtime allocation) ----------------
__device__ __align__(128) float         g_S[(size_t)N_NODES * NHID];     // fp32 GEMM out / SpMM in
__device__ __align__(128) __nv_bfloat16 g_xh[(size_t)N_NODES * NFEAT];
__device__ __align__(128) __nv_bfloat16 g_xl[(size_t)N_NODES * NFEAT];
__device__ __align__(128) __nv_bfloat16 g_hh[(size_t)N_NODES * NHID];
__device__ __align__(128) __nv_bfloat16 g_hl[(size_t)N_NODES * NHID];
__device__ __align__(128) __nv_bfloat16 g_w1t_h[KDIM * NHID], g_w1t_l[KDIM * NHID]; // W1^T [N,K]
__device__ __align__(128) __nv_bfloat16 g_w2t_h[KDIM * NHID], g_w2t_l[KDIM * NHID]; // W2^T
__device__ __align__(128) __nv_bfloat16 g_wht_h[128 * KDIM],  g_wht_l[128 * KDIM];  // [WL1|WL2]^T
__device__ float g_headb[2 * NCLASS];
__device__ int   g_row_ptr[N_NODES + 1];

// ---------------- small PTX helpers ----------------
__device__ __forceinline__ void cp16(uint32_t s, const __nv_bfloat16* g, bool v) {
    int sz = v ? 16 : 0;
    asm volatile("cp.async.cg.shared.global [%0], [%1], 16, %2;"
                 :: "r"(s), "l"(__cvta_generic_to_global(g)), "r"(sz));
}
#define CP_COMMIT() asm volatile("cp.async.commit_group;" ::: "memory")

__device__ __forceinline__ void ldsm4(uint32_t* r, uint32_t a) {
    asm volatile("ldmatrix.sync.aligned.m8n8.x4.shared.b16 {%0,%1,%2,%3}, [%4];"
                 : "=r"(r[0]), "=r"(r[1]), "=r"(r[2]), "=r"(r[3]) : "r"(a));
}
__device__ __forceinline__ void mma16816(float* c, const uint32_t* a, const uint32_t* b) {
    asm volatile("mma.sync.aligned.m16n8k16.row.col.f32.bf16.bf16.f32 "
                 "{%0,%1,%2,%3}, {%4,%5,%6,%7}, {%8,%9}, {%0,%1,%2,%3};"
                 : "+f"(c[0]), "+f"(c[1]), "+f"(c[2]), "+f"(c[3])
                 : "r"(a[0]), "r"(a[1]), "r"(a[2]), "r"(a[3]), "r"(b[0]), "r"(b[1]));
}

// ---------------- CSR row_ptr from sorted edge_dst ----------------
__global__ void build_row_ptr_kernel(const int* __restrict__ dst, int n_edges) {
    int i = blockIdx.x * blockDim.x + threadIdx.x;
    if (i > N_NODES) return;
    int lo = 0, hi = n_edges;
    while (lo < hi) {
        int mid = (lo + hi) >> 1;
        if (dst[mid] < i) lo = mid + 1; else hi = mid;
    }
    g_row_ptr[i] = lo;
}

// ---------------- weight prep: transpose + bf16 split ----------------
__device__ __forceinline__ void split_store(__nv_bfloat16* ph, __nv_bfloat16* pl, float v) {
    __nv_bfloat16 hi = __float2bfloat16(v);
    *ph = hi;
    *pl = __float2bfloat16(v - __bfloat162float(hi));
}
__global__ void prep_w_kernel(const float* __restrict__ W1, const float* __restrict__ W2,
                              const float* __restrict__ WL1, const float* __restrict__ WL2,
                              const float* __restrict__ bL1, const float* __restrict__ bL2) {
    int i = blockIdx.x * blockDim.x + threadIdx.x;
    if (i < KDIM * NHID) {
        int n = i >> 8, k = i & 255;
        split_store(&g_w1t_h[i], &g_w1t_l[i], W1[k * NHID + n]);
        split_store(&g_w2t_h[i], &g_w2t_l[i], W2[k * NHID + n]);
    }
    if (i < 128 * KDIM) {
        int n = i >> 8, k = i & 255;
        float v = (n < NCLASS) ? WL1[k * NCLASS + n] : WL2[k * NCLASS + (n - NCLASS)];
        split_store(&g_wht_h[i], &g_wht_l[i], v);
    }
    if (i < 2 * NCLASS)
        g_headb[i] = (i < NCLASS) ? bL1[i] : bL2[i - NCLASS];
}

// ---------------- x -> bf16 hi/lo ----------------
__global__ void convert_x_kernel(const float* __restrict__ x) {
    int i = blockIdx.x * blockDim.x + threadIdx.x;
    if (i >= N_NODES * NFEAT) return;
    split_store(&g_xh[i], &g_xl[i], x[i]);
}

// ---------------- mma.sync split-bf16 GEMM (R11 config: CTA 128x128, KC=32, 2 CTA/SM) ----------------
// C = (Ah+Al) @ (Bh+Bl)^T via AhBh + AhBl + AlBh, fp32 accum.
// A: [M,256] bf16 row-major; B: [Nrows,256] bf16 row-major (= W^T, K-major).
// K-chunk 32, 2-stage cp.async pipeline; warps 2(M) x 4(N), warp tile 64x32.
// Stage = 40KB -> 2 stages = 80KB -> 2 CTAs/SM resident (phase interleave).
constexpr int KC     = 32;
constexpr int ROWB   = 80;             // (32+8) halves * 2B; 8-row ldsm conflict-free
constexpr int TILEB  = 128 * ROWB;     // 10240
constexpr int STAGEB = 4 * TILEB;      // 40960  (tiles: Ah, Al, Bh, Bl)
constexpr int GEMM_SMEM = 2 * STAGEB;  // 81920  (2 CTAs/SM fit in 228KB)

template <bool HEAD>
__global__ void __launch_bounds__(256, 2) gemm_mma_kernel(
    const __nv_bfloat16* __restrict__ Ah, const __nv_bfloat16* __restrict__ Al,
    const __nv_bfloat16* __restrict__ Bh, const __nv_bfloat16* __restrict__ Bl,
    float* __restrict__ out, int M, int ldC)
{
    extern __shared__ __align__(128) char smem[];
    const int tid = threadIdx.x, lane = tid & 31, wid = tid >> 5;
    const int wm = wid >> 2, wn = wid & 3;            // 2(M) x 4(N) warps, warp tile 64x32
    const int m0 = blockIdx.y * 128;
    const int n0 = blockIdx.x * 128;
    const __nv_bfloat16* BhO = Bh + (size_t)n0 * KDIM;
    const __nv_bfloat16* BlO = Bl + (size_t)n0 * KDIM;
    uint32_t sb = (uint32_t)__cvta_generic_to_shared(smem);

    float acc[4][4][4];
#pragma unroll
    for (int a = 0; a < 4; a++)
#pragma unroll
        for (int b = 0; b < 4; b++)
#pragma unroll
            for (int c = 0; c < 4; c++) acc[a][b][c] = 0.f;

    // stage loader: 4 tiles x 128 rows x 4 chunks(16B) = 2048 cp.async
    auto load_stage = [&](int stage, int kc) {
        uint32_t base = sb + stage * STAGEB;
        for (int i = tid; i < 2048; i += 256) {
            int t = i >> 9, rc = i & 511, r = rc >> 2, ch = rc & 3;
            const __nv_bfloat16* src;
            bool v = true;
            if (t == 0)      { src = Ah  + (size_t)(m0 + r) * KDIM + kc + ch * 8; v = (m0 + r) < M; }
            else if (t == 1) { src = Al  + (size_t)(m0 + r) * KDIM + kc + ch * 8; v = (m0 + r) < M; }
            else if (t == 2) { src = BhO + (size_t)r * KDIM + kc + ch * 8; }
            else             { src = BlO + (size_t)r * KDIM + kc + ch * 8; }
            cp16(base + t * TILEB + r * ROWB + ch * 16, src, v);
        }
    };

    const int ar  = lane & 15;
    const int acx = ((lane >> 4) & 1) * 8;
    const int br  = ((lane >> 4) << 3) + (lane & 7);
    const int bc  = ((lane >> 3) & 1) * 8;

    auto compute = [&](int stage) {
        uint32_t aH = sb + stage * STAGEB;
        uint32_t aL = aH + TILEB;
        uint32_t bH = aH + 2 * TILEB;
        uint32_t bL = aH + 3 * TILEB;
#pragma unroll
        for (int k16 = 0; k16 < KC / 16; k16++) {
            uint32_t ah[4][4], al[4][4], bh[4][2], bl[4][2];
#pragma unroll
            for (int mf = 0; mf < 4; mf++) {
                uint32_t off = (uint32_t)((wm * 64 + mf * 16 + ar) * ROWB + (acx + k16 * 16) * 2);
                ldsm4(ah[mf], aH + off);
                ldsm4(al[mf], aL + off);
            }
#pragma unroll
            for (int np = 0; np < 2; np++) {
                uint32_t off = (uint32_t)((wn * 32 + np * 16 + br) * ROWB + (bc + k16 * 16) * 2);
                uint32_t t[4];
                ldsm4(t, bH + off);
                bh[np*2][0] = t[0]; bh[np*2][1] = t[1]; bh[np*2+1][0] = t[2]; bh[np*2+1][1] = t[3];
                ldsm4(t, bL + off);
                bl[np*2][0] = t[0]; bl[np*2][1] = t[1]; bl[np*2+1][0] = t[2]; bl[np*2+1][1] = t[3];
            }
#pragma unroll
            for (int mf = 0; mf < 4; mf++)
#pragma unroll
                for (int nf = 0; nf < 4; nf++) {
                    mma16816(acc[mf][nf], ah[mf], bh[nf]);
                    mma16816(acc[mf][nf], ah[mf], bl[nf]);
                    mma16816(acc[mf][nf], al[mf], bh[nf]);
                }
        }
    };

    constexpr int NIT = KDIM / KC;   // 8
    load_stage(0, 0);
    CP_COMMIT();
#pragma unroll
    for (int it = 0; it < NIT; it++) {
        if (it + 1 < NIT) {
            load_stage((it + 1) & 1, (it + 1) * KC);
            CP_COMMIT();
            asm volatile("cp.async.wait_group 1;" ::: "memory");
        } else {
            asm volatile("cp.async.wait_group 0;" ::: "memory");
        }
        __syncthreads();
        compute(it & 1);
        __syncthreads();
    }

    // ---- epilogue ----
#pragma unroll
    for (int mf = 0; mf < 4; mf++) {
        int rbase = m0 + wm * 64 + mf * 16 + (lane >> 2);
#pragma unroll
        for (int nf = 0; nf < 4; nf++) {
            int col = (HEAD ? 0 : n0) + wn * 32 + nf * 8 + (lane & 3) * 2;
#pragma unroll
            for (int h = 0; h < 2; h++) {
                int row = rbase + h * 8;
                if (row >= M) continue;
                float2 v = make_float2(acc[mf][nf][h * 2], acc[mf][nf][h * 2 + 1]);
                if (!HEAD) {
                    *(float2*)(out + (size_t)row * ldC + col) = v;
                } else {
                    v.x += g_headb[col]; v.y += g_headb[col + 1];
                    float* dst = (col < NCLASS)
                        ? out + (size_t)row * NCLASS + col
                        : out + (size_t)N_NODES * NCLASS + (size_t)row * NCLASS + (col - NCLASS);
                    *(float2*)dst = v;
                }
            }
        }
    }
}

// ---------------- SpMM + bias + relu -> bf16 hi/lo split (both halves in one launch) ----------------
// blockIdx.y selects the 128-col half (working set 51MB each -> L2-resident).
struct __align__(8) bf16x4 { __nv_bfloat162 a, b; };
__device__ __forceinline__ void emit4(__nv_bfloat16* Hh, __nv_bfloat16* Hl, size_t idx,
                                      float4 acc, float4 bia) {
    float v0 = fmaxf(acc.x + bia.x, 0.f), v1 = fmaxf(acc.y + bia.y, 0.f);
    float v2 = fmaxf(acc.z + bia.z, 0.f), v3 = fmaxf(acc.w + bia.w, 0.f);
    __nv_bfloat16 h0 = __float2bfloat16(v0), h1 = __float2bfloat16(v1);
    __nv_bfloat16 h2 = __float2bfloat16(v2), h3 = __float2bfloat16(v3);
    bf16x4 hv; hv.a = __nv_bfloat162(h0, h1); hv.b = __nv_bfloat162(h2, h3);
    *(bf16x4*)(Hh + idx) = hv;
    bf16x4 lv;
    lv.a = __nv_bfloat162(__float2bfloat16(v0 - __bfloat162float(h0)),
                          __float2bfloat16(v1 - __bfloat162float(h1)));
    lv.b = __nv_bfloat162(__float2bfloat16(v2 - __bfloat162float(h2)),
                          __float2bfloat16(v3 - __bfloat162float(h3)));
    *(bf16x4*)(Hl + idx) = lv;
}

__device__ __forceinline__ void fma4(float4& acc, float s, const float4& v) {
    acc.x += s * v.x; acc.y += s * v.y; acc.z += s * v.z; acc.w += s * v.w;
}

__global__ void __launch_bounds__(256) spmm_relu_kernel(
    const float* __restrict__ S, const int* __restrict__ src,
    const float* __restrict__ w, const float* __restrict__ bias,
    __nv_bfloat16* __restrict__ Hh, __nv_bfloat16* __restrict__ Hl)
{
    int node = (blockIdx.x * blockDim.x + threadIdx.x) >> 5;
    if (node >= N_NODES) return;
    int lane = threadIdx.x & 31;
    int colOff = blockIdx.y * 128;
    int e0 = g_row_ptr[node], e1 = g_row_ptr[node + 1];
    const float* Sc = S + colOff + lane * 4;

    float4 acc = make_float4(0.f, 0.f, 0.f, 0.f);
    int e = e0;
    for (; e + 4 <= e1; e += 4) {
        int   s0 = __ldg(src + e),     s1 = __ldg(src + e + 1);
        int   s2 = __ldg(src + e + 2), s3 = __ldg(src + e + 3);
        float w0 = __ldg(w + e),     w1 = __ldg(w + e + 1);
        float w2 = __ldg(w + e + 2), w3 = __ldg(w + e + 3);
        float4 a0 = __ldg((const float4*)(Sc + (size_t)s0 * NHID));
        float4 a1 = __ldg((const float4*)(Sc + (size_t)s1 * NHID));
        float4 a2 = __ldg((const float4*)(Sc + (size_t)s2 * NHID));
        float4 a3 = __ldg((const float4*)(Sc + (size_t)s3 * NHID));
        fma4(acc, w0, a0); fma4(acc, w1, a1); fma4(acc, w2, a2); fma4(acc, w3, a3);
    }
    for (; e < e1; e++) {
        int   s  = __ldg(src + e);
        float sw = __ldg(w + e);
        float4 a = __ldg((const float4*)(Sc + (size_t)s * NHID));
        fma4(acc, sw, a);
    }

    float4 bia = *(const float4*)(bias + colOff + lane * 4);
    emit4(Hh, Hl, (size_t)node * NHID + colOff + lane * 4, acc, bia);
}

// ---------------- launch ----------------
extern "C" void kernel_launch(void* const* d_in, const int* in_sizes, int n_in,
                              void* d_out, int out_size) {
    const float* x   = (const float*)d_in[0];
    const int*   es  = (const int*)  d_in[1];
    const int*   ed  = (const int*)  d_in[2];
    const float* ew  = (const float*)d_in[3];
    const float* W1  = (const float*)d_in[4];
    const float* b1  = (const float*)d_in[5];
    const float* W2  = (const float*)d_in[6];
    const float* b2  = (const float*)d_in[7];
    const float* WL1 = (const float*)d_in[8];
    const float* bL1 = (const float*)d_in[9];
    const float* WL2 = (const float*)d_in[10];
    const float* bL2 = (const float*)d_in[11];
    int n_edges = in_sizes[1];

    float *S; __nv_bfloat16 *xh, *xl, *hh, *hl, *w1h, *w1l, *w2h, *w2l, *whh, *whl;
    cudaGetSymbolAddress((void**)&S,   g_S);
    cudaGetSymbolAddress((void**)&xh,  g_xh);    cudaGetSymbolAddress((void**)&xl,  g_xl);
    cudaGetSymbolAddress((void**)&hh,  g_hh);    cudaGetSymbolAddress((void**)&hl,  g_hl);
    cudaGetSymbolAddress((void**)&w1h, g_w1t_h); cudaGetSymbolAddress((void**)&w1l, g_w1t_l);
    cudaGetSymbolAddress((void**)&w2h, g_w2t_h); cudaGetSymbolAddress((void**)&w2l, g_w2t_l);
    cudaGetSymbolAddress((void**)&whh, g_wht_h); cudaGetSymbolAddress((void**)&whl, g_wht_l);

    cudaFuncSetAttribute(gemm_mma_kernel<false>,
                         cudaFuncAttributeMaxDynamicSharedMemorySize, GEMM_SMEM);
    cudaFuncSetAttribute(gemm_mma_kernel<true>,
                         cudaFuncAttributeMaxDynamicSharedMemorySize, GEMM_SMEM);

    const int MTILES = (N_NODES + 127) / 128;   // 782
    const int spmm_blocks = (N_NODES + 7) / 8;  // 8 warps/block

    build_row_ptr_kernel<<<(N_NODES + 256) / 256, 256>>>(ed, n_edges);
    prep_w_kernel<<<(KDIM * NHID + 255) / 256, 256>>>(W1, W2, WL1, WL2, bL1, bL2);
    convert_x_kernel<<<(N_NODES * NFEAT + 255) / 256, 256>>>(x);

    // layer 1
    gemm_mma_kernel<false><<<dim3(2, MTILES), 256, GEMM_SMEM>>>(xh, xl, w1h, w1l, S, N_NODES, NHID);
    spmm_relu_kernel<<<dim3(spmm_blocks, 2), 256>>>(S, es, ew, b1, hh, hl);
    // layer 2
    gemm_mma_kernel<false><<<dim3(2, MTILES), 256, GEMM_SMEM>>>(hh, hl, w2h, w2l, S, N_NODES, NHID);
    spmm_relu_kernel<<<dim3(spmm_blocks, 2), 256>>>(S, es, ew, b2, hh, hl);
    // twin heads
    gemm_mma_kernel<true><<<dim3(1, MTILES), 256, GEMM_SMEM>>>(hh, hl, whh, whl, (float*)d_out, N_NODES, 128);
}

// round 15
// speedup vs baseline: 2.6238x; 1.1922x over previous
#include <cuda_runtime.h>
#include <cuda_bf16.h>
#include <cuda_fp16.h>
#include <cstdint>

#define N_NODES 100000
#define NFEAT   256
#define NHID    256
#define NCLASS  64
#define KDIM    256

// ---------------- scratch (device globals; no runtime allocation) ----------------
__device__ __align__(128) __half        g_S16[(size_t)N_NODES * NHID];   // fp16 GEMM out / SpMM in
__device__ __align__(128) __nv_bfloat16 g_xh[(size_t)N_NODES * NFEAT];
__device__ __align__(128) __nv_bfloat16 g_xl[(size_t)N_NODES * NFEAT];
__device__ __align__(128) __nv_bfloat16 g_hh[(size_t)N_NODES * NHID];
__device__ __align__(128) __nv_bfloat16 g_hl[(size_t)N_NODES * NHID];
__device__ __align__(128) __nv_bfloat16 g_w1t_h[KDIM * NHID], g_w1t_l[KDIM * NHID]; // W1^T [N,K]
__device__ __align__(128) __nv_bfloat16 g_w2t_h[KDIM * NHID], g_w2t_l[KDIM * NHID]; // W2^T
__device__ __align__(128) __nv_bfloat16 g_wht_h[128 * KDIM],  g_wht_l[128 * KDIM];  // [WL1|WL2]^T
__device__ float g_headb[2 * NCLASS];
__device__ int   g_row_ptr[N_NODES + 1];

// ---------------- small PTX helpers ----------------
__device__ __forceinline__ void cp16(uint32_t s, const __nv_bfloat16* g, bool v) {
    int sz = v ? 16 : 0;
    asm volatile("cp.async.cg.shared.global [%0], [%1], 16, %2;"
                 :: "r"(s), "l"(__cvta_generic_to_global(g)), "r"(sz));
}
#define CP_COMMIT() asm volatile("cp.async.commit_group;" ::: "memory")

__device__ __forceinline__ void ldsm4(uint32_t* r, uint32_t a) {
    asm volatile("ldmatrix.sync.aligned.m8n8.x4.shared.b16 {%0,%1,%2,%3}, [%4];"
                 : "=r"(r[0]), "=r"(r[1]), "=r"(r[2]), "=r"(r[3]) : "r"(a));
}
__device__ __forceinline__ void mma16816(float* c, const uint32_t* a, const uint32_t* b) {
    asm volatile("mma.sync.aligned.m16n8k16.row.col.f32.bf16.bf16.f32 "
                 "{%0,%1,%2,%3}, {%4,%5,%6,%7}, {%8,%9}, {%0,%1,%2,%3};"
                 : "+f"(c[0]), "+f"(c[1]), "+f"(c[2]), "+f"(c[3])
                 : "r"(a[0]), "r"(a[1]), "r"(a[2]), "r"(a[3]), "r"(b[0]), "r"(b[1]));
}

// ---------------- CSR row_ptr from sorted edge_dst ----------------
__global__ void build_row_ptr_kernel(const int* __restrict__ dst, int n_edges) {
    int i = blockIdx.x * blockDim.x + threadIdx.x;
    if (i > N_NODES) return;
    int lo = 0, hi = n_edges;
    while (lo < hi) {
        int mid = (lo + hi) >> 1;
        if (dst[mid] < i) lo = mid + 1; else hi = mid;
    }
    g_row_ptr[i] = lo;
}

// ---------------- weight prep: transpose + bf16 split ----------------
__device__ __forceinline__ void split_store(__nv_bfloat16* ph, __nv_bfloat16* pl, float v) {
    __nv_bfloat16 hi = __float2bfloat16(v);
    *ph = hi;
    *pl = __float2bfloat16(v - __bfloat162float(hi));
}
__global__ void prep_w_kernel(const float* __restrict__ W1, const float* __restrict__ W2,
                              const float* __restrict__ WL1, const float* __restrict__ WL2,
                              const float* __restrict__ bL1, const float* __restrict__ bL2) {
    int i = blockIdx.x * blockDim.x + threadIdx.x;
    if (i < KDIM * NHID) {
        int n = i >> 8, k = i & 255;
        split_store(&g_w1t_h[i], &g_w1t_l[i], W1[k * NHID + n]);
        split_store(&g_w2t_h[i], &g_w2t_l[i], W2[k * NHID + n]);
    }
    if (i < 128 * KDIM) {
        int n = i >> 8, k = i & 255;
        float v = (n < NCLASS) ? WL1[k * NCLASS + n] : WL2[k * NCLASS + (n - NCLASS)];
        split_store(&g_wht_h[i], &g_wht_l[i], v);
    }
    if (i < 2 * NCLASS)
        g_headb[i] = (i < NCLASS) ? bL1[i] : bL2[i - NCLASS];
}

// ---------------- x -> bf16 hi/lo ----------------
__global__ void convert_x_kernel(const float* __restrict__ x) {
    int i = blockIdx.x * blockDim.x + threadIdx.x;
    if (i >= N_NODES * NFEAT) return;
    split_store(&g_xh[i], &g_xl[i], x[i]);
}

// ---------------- mma.sync split-bf16 GEMM (CTA 128x128, KC=32, 2 CTA/SM) ----------------
// C = (Ah+Al) @ (Bh+Bl)^T via AhBh + AhBl + AlBh, fp32 accum.
// !HEAD: writes fp16 S (256-col). HEAD: writes fp32 logits with bias + split cols.
constexpr int KC     = 32;
constexpr int ROWB   = 80;             // (32+8) halves * 2B; 8-row ldsm conflict-free
constexpr int TILEB  = 128 * ROWB;     // 10240
constexpr int STAGEB = 4 * TILEB;      // 40960  (tiles: Ah, Al, Bh, Bl)
constexpr int GEMM_SMEM = 2 * STAGEB;  // 81920  (2 CTAs/SM)

template <bool HEAD>
__global__ void __launch_bounds__(256, 2) gemm_mma_kernel(
    const __nv_bfloat16* __restrict__ Ah, const __nv_bfloat16* __restrict__ Al,
    const __nv_bfloat16* __restrict__ Bh, const __nv_bfloat16* __restrict__ Bl,
    void* __restrict__ out_v, int M, int ldC)
{
    extern __shared__ __align__(128) char smem[];
    const int tid = threadIdx.x, lane = tid & 31, wid = tid >> 5;
    const int wm = wid >> 2, wn = wid & 3;            // 2(M) x 4(N) warps, warp tile 64x32
    const int m0 = blockIdx.y * 128;
    const int n0 = blockIdx.x * 128;
    const __nv_bfloat16* BhO = Bh + (size_t)n0 * KDIM;
    const __nv_bfloat16* BlO = Bl + (size_t)n0 * KDIM;
    uint32_t sb = (uint32_t)__cvta_generic_to_shared(smem);

    float acc[4][4][4];
#pragma unroll
    for (int a = 0; a < 4; a++)
#pragma unroll
        for (int b = 0; b < 4; b++)
#pragma unroll
            for (int c = 0; c < 4; c++) acc[a][b][c] = 0.f;

    auto load_stage = [&](int stage, int kc) {
        uint32_t base = sb + stage * STAGEB;
        for (int i = tid; i < 2048; i += 256) {
            int t = i >> 9, rc = i & 511, r = rc >> 2, ch = rc & 3;
            const __nv_bfloat16* src;
            bool v = true;
            if (t == 0)      { src = Ah  + (size_t)(m0 + r) * KDIM + kc + ch * 8; v = (m0 + r) < M; }
            else if (t == 1) { src = Al  + (size_t)(m0 + r) * KDIM + kc + ch * 8; v = (m0 + r) < M; }
            else if (t == 2) { src = BhO + (size_t)r * KDIM + kc + ch * 8; }
            else             { src = BlO + (size_t)r * KDIM + kc + ch * 8; }
            cp16(base + t * TILEB + r * ROWB + ch * 16, src, v);
        }
    };

    const int ar  = lane & 15;
    const int acx = ((lane >> 4) & 1) * 8;
    const int br  = ((lane >> 4) << 3) + (lane & 7);
    const int bc  = ((lane >> 3) & 1) * 8;

    auto compute = [&](int stage) {
        uint32_t aH = sb + stage * STAGEB;
        uint32_t aL = aH + TILEB;
        uint32_t bH = aH + 2 * TILEB;
        uint32_t bL = aH + 3 * TILEB;
#pragma unroll
        for (int k16 = 0; k16 < KC / 16; k16++) {
            uint32_t ah[4][4], al[4][4], bh[4][2], bl[4][2];
#pragma unroll
            for (int mf = 0; mf < 4; mf++) {
                uint32_t off = (uint32_t)((wm * 64 + mf * 16 + ar) * ROWB + (acx + k16 * 16) * 2);
                ldsm4(ah[mf], aH + off);
                ldsm4(al[mf], aL + off);
            }
#pragma unroll
            for (int np = 0; np < 2; np++) {
                uint32_t off = (uint32_t)((wn * 32 + np * 16 + br) * ROWB + (bc + k16 * 16) * 2);
                uint32_t t[4];
                ldsm4(t, bH + off);
                bh[np*2][0] = t[0]; bh[np*2][1] = t[1]; bh[np*2+1][0] = t[2]; bh[np*2+1][1] = t[3];
                ldsm4(t, bL + off);
                bl[np*2][0] = t[0]; bl[np*2][1] = t[1]; bl[np*2+1][0] = t[2]; bl[np*2+1][1] = t[3];
            }
#pragma unroll
            for (int mf = 0; mf < 4; mf++)
#pragma unroll
                for (int nf = 0; nf < 4; nf++) {
                    mma16816(acc[mf][nf], ah[mf], bh[nf]);
                    mma16816(acc[mf][nf], ah[mf], bl[nf]);
                    mma16816(acc[mf][nf], al[mf], bh[nf]);
                }
        }
    };

    constexpr int NIT = KDIM / KC;   // 8
    load_stage(0, 0);
    CP_COMMIT();
#pragma unroll
    for (int it = 0; it < NIT; it++) {
        if (it + 1 < NIT) {
            load_stage((it + 1) & 1, (it + 1) * KC);
            CP_COMMIT();
            asm volatile("cp.async.wait_group 1;" ::: "memory");
        } else {
            asm volatile("cp.async.wait_group 0;" ::: "memory");
        }
        __syncthreads();
        compute(it & 1);
        __syncthreads();
    }

    // ---- epilogue ----
#pragma unroll
    for (int mf = 0; mf < 4; mf++) {
        int rbase = m0 + wm * 64 + mf * 16 + (lane >> 2);
#pragma unroll
        for (int nf = 0; nf < 4; nf++) {
            int col = (HEAD ? 0 : n0) + wn * 32 + nf * 8 + (lane & 3) * 2;
#pragma unroll
            for (int h = 0; h < 2; h++) {
                int row = rbase + h * 8;
                if (row >= M) continue;
                float2 v = make_float2(acc[mf][nf][h * 2], acc[mf][nf][h * 2 + 1]);
                if (!HEAD) {
                    __half* o = (__half*)out_v;
                    *(__half2*)(o + (size_t)row * ldC + col) = __floats2half2_rn(v.x, v.y);
                } else {
                    float* o = (float*)out_v;
                    v.x += g_headb[col]; v.y += g_headb[col + 1];
                    float* dst = (col < NCLASS)
                        ? o + (size_t)row * NCLASS + col
                        : o + (size_t)N_NODES * NCLASS + (size_t)row * NCLASS + (col - NCLASS);
                    *(float2*)dst = v;
                }
            }
        }
    }
}

// ---------------- SpMM (fp16 gather, full 256 cols, single pass) + bias + relu -> bf16 hi/lo ----------------
// Working set = 100k x 256 fp16 = 51MB -> fully L2-resident; one LDG.128 per edge per lane.
struct __align__(8) bf16x4 { __nv_bfloat162 a, b; };
__device__ __forceinline__ void emit4(__nv_bfloat16* Hh, __nv_bfloat16* Hl, size_t idx,
                                      const float* acc, const float4 bia) {
    float v0 = fmaxf(acc[0] + bia.x, 0.f), v1 = fmaxf(acc[1] + bia.y, 0.f);
    float v2 = fmaxf(acc[2] + bia.z, 0.f), v3 = fmaxf(acc[3] + bia.w, 0.f);
    __nv_bfloat16 h0 = __float2bfloat16(v0), h1 = __float2bfloat16(v1);
    __nv_bfloat16 h2 = __float2bfloat16(v2), h3 = __float2bfloat16(v3);
    bf16x4 hv; hv.a = __nv_bfloat162(h0, h1); hv.b = __nv_bfloat162(h2, h3);
    *(bf16x4*)(Hh + idx) = hv;
    bf16x4 lv;
    lv.a = __nv_bfloat162(__float2bfloat16(v0 - __bfloat162float(h0)),
                          __float2bfloat16(v1 - __bfloat162float(h1)));
    lv.b = __nv_bfloat162(__float2bfloat16(v2 - __bfloat162float(h2)),
                          __float2bfloat16(v3 - __bfloat162float(h3)));
    *(bf16x4*)(Hl + idx) = lv;
}

__device__ __forceinline__ void acc_edge(float* acc, float w, const uint4& q) {
    const __half2* hp = (const __half2*)&q;
#pragma unroll
    for (int j = 0; j < 4; j++) {
        float2 f = __half22float2(hp[j]);
        acc[2 * j] += w * f.x;
        acc[2 * j + 1] += w * f.y;
    }
}

__global__ void __launch_bounds__(256) spmm_relu_kernel(
    const __half* __restrict__ S, const int* __restrict__ src,
    const float* __restrict__ w, const float* __restrict__ bias,
    __nv_bfloat16* __restrict__ Hh, __nv_bfloat16* __restrict__ Hl)
{
    int node = (blockIdx.x * blockDim.x + threadIdx.x) >> 5;
    if (node >= N_NODES) return;
    int lane = threadIdx.x & 31;
    int e0 = g_row_ptr[node], e1 = g_row_ptr[node + 1];
    const __half* Sc = S + lane * 8;   // 8 fp16 cols per lane = 16B

    float acc[8];
#pragma unroll
    for (int j = 0; j < 8; j++) acc[j] = 0.f;

    int e = e0;
    for (; e + 4 <= e1; e += 4) {
        int   s0 = __ldg(src + e),     s1 = __ldg(src + e + 1);
        int   s2 = __ldg(src + e + 2), s3 = __ldg(src + e + 3);
        float w0 = __ldg(w + e),     w1 = __ldg(w + e + 1);
        float w2 = __ldg(w + e + 2), w3 = __ldg(w + e + 3);
        uint4 q0 = __ldg((const uint4*)(Sc + (size_t)s0 * NHID));
        uint4 q1 = __ldg((const uint4*)(Sc + (size_t)s1 * NHID));
        uint4 q2 = __ldg((const uint4*)(Sc + (size_t)s2 * NHID));
        uint4 q3 = __ldg((const uint4*)(Sc + (size_t)s3 * NHID));
        acc_edge(acc, w0, q0); acc_edge(acc, w1, q1);
        acc_edge(acc, w2, q2); acc_edge(acc, w3, q3);
    }
    for (; e < e1; e++) {
        int   s  = __ldg(src + e);
        float sw = __ldg(w + e);
        uint4 q = __ldg((const uint4*)(Sc + (size_t)s * NHID));
        acc_edge(acc, sw, q);
    }

    float4 b0 = *(const float4*)(bias + lane * 8);
    float4 b1 = *(const float4*)(bias + lane * 8 + 4);
    emit4(Hh, Hl, (size_t)node * NHID + lane * 8, acc, b0);
    emit4(Hh, Hl, (size_t)node * NHID + lane * 8 + 4, acc + 4, b1);
}

// ---------------- launch ----------------
extern "C" void kernel_launch(void* const* d_in, const int* in_sizes, int n_in,
                              void* d_out, int out_size) {
    const float* x   = (const float*)d_in[0];
    const int*   es  = (const int*)  d_in[1];
    const int*   ed  = (const int*)  d_in[2];
    const float* ew  = (const float*)d_in[3];
    const float* W1  = (const float*)d_in[4];
    const float* b1  = (const float*)d_in[5];
    const float* W2  = (const float*)d_in[6];
    const float* b2  = (const float*)d_in[7];
    const float* WL1 = (const float*)d_in[8];
    const float* bL1 = (const float*)d_in[9];
    const float* WL2 = (const float*)d_in[10];
    const float* bL2 = (const float*)d_in[11];
    int n_edges = in_sizes[1];

    __half *S; __nv_bfloat16 *xh, *xl, *hh, *hl, *w1h, *w1l, *w2h, *w2l, *whh, *whl;
    cudaGetSymbolAddress((void**)&S,   g_S16);
    cudaGetSymbolAddress((void**)&xh,  g_xh);    cudaGetSymbolAddress((void**)&xl,  g_xl);
    cudaGetSymbolAddress((void**)&hh,  g_hh);    cudaGetSymbolAddress((void**)&hl,  g_hl);
    cudaGetSymbolAddress((void**)&w1h, g_w1t_h); cudaGetSymbolAddress((void**)&w1l, g_w1t_l);
    cudaGetSymbolAddress((void**)&w2h, g_w2t_h); cudaGetSymbolAddress((void**)&w2l, g_w2t_l);
    cudaGetSymbolAddress((void**)&whh, g_wht_h); cudaGetSymbolAddress((void**)&whl, g_wht_l);

    cudaFuncSetAttribute(gemm_mma_kernel<false>,
                         cudaFuncAttributeMaxDynamicSharedMemorySize, GEMM_SMEM);
    cudaFuncSetAttribute(gemm_mma_kernel<true>,
                         cudaFuncAttributeMaxDynamicSharedMemorySize, GEMM_SMEM);

    const int MTILES = (N_NODES + 127) / 128;   // 782
    const int spmm_blocks = (N_NODES + 7) / 8;  // 8 warps/block

    build_row_ptr_kernel<<<(N_NODES + 256) / 256, 256>>>(ed, n_edges);
    prep_w_kernel<<<(KDIM * NHID + 255) / 256, 256>>>(W1, W2, WL1, WL2, bL1, bL2);
    convert_x_kernel<<<(N_NODES * NFEAT + 255) / 256, 256>>>(x);

    // layer 1
    gemm_mma_kernel<false><<<dim3(2, MTILES), 256, GEMM_SMEM>>>(xh, xl, w1h, w1l, S, N_NODES, NHID);
    spmm_relu_kernel<<<spmm_blocks, 256>>>(S, es, ew, b1, hh, hl);
    // layer 2
    gemm_mma_kernel<false><<<dim3(2, MTILES), 256, GEMM_SMEM>>>(hh, hl, w2h, w2l, S, N_NODES, NHID);
    spmm_relu_kernel<<<spmm_blocks, 256>>>(S, es, ew, b2, hh, hl);
    // twin heads
    gemm_mma_kernel<true><<<dim3(1, MTILES), 256, GEMM_SMEM>>>(hh, hl, whh, whl, d_out, N_NODES, 128);
}

// round 16
// speedup vs baseline: 2.9273x; 1.1157x over previous
#include <cuda_runtime.h>
#include <cuda_bf16.h>
#include <cuda_fp16.h>
#include <cstdint>

#define N_NODES 100000
#define NFEAT   256
#define NHID    256
#define NCLASS  64
#define KDIM    256

// ---------------- scratch (device globals; no runtime allocation) ----------------
__device__ __align__(128) __half        g_S16[(size_t)N_NODES * NHID];   // fp16 GEMM out / SpMM in
__device__ __align__(128) __half        g_h16[(size_t)N_NODES * NHID];   // fp16 h2 (head input)
__device__ __align__(128) __nv_bfloat16 g_xh[(size_t)N_NODES * NFEAT];
__device__ __align__(128) __nv_bfloat16 g_xl[(size_t)N_NODES * NFEAT];
__device__ __align__(128) __nv_bfloat16 g_hh[(size_t)N_NODES * NHID];
__device__ __align__(128) __nv_bfloat16 g_hl[(size_t)N_NODES * NHID];
__device__ __align__(128) __nv_bfloat16 g_w1t_h[KDIM * NHID], g_w1t_l[KDIM * NHID]; // W1^T [N,K]
__device__ __align__(128) __nv_bfloat16 g_w2t_h[KDIM * NHID], g_w2t_l[KDIM * NHID]; // W2^T
__device__ __align__(128) __half        g_whH[128 * KDIM], g_whL[128 * KDIM];       // [WL1|WL2]^T fp16 hi/lo
__device__ float g_headb[2 * NCLASS];
__device__ int   g_row_ptr[N_NODES + 1];

// ---------------- small PTX helpers ----------------
__device__ __forceinline__ void cp16(uint32_t s, const void* g, bool v) {
    int sz = v ? 16 : 0;
    asm volatile("cp.async.cg.shared.global [%0], [%1], 16, %2;"
                 :: "r"(s), "l"(__cvta_generic_to_global(g)), "r"(sz));
}
#define CP_COMMIT() asm volatile("cp.async.commit_group;" ::: "memory")

__device__ __forceinline__ void ldsm4(uint32_t* r, uint32_t a) {
    asm volatile("ldmatrix.sync.aligned.m8n8.x4.shared.b16 {%0,%1,%2,%3}, [%4];"
                 : "=r"(r[0]), "=r"(r[1]), "=r"(r[2]), "=r"(r[3]) : "r"(a));
}
__device__ __forceinline__ void mma16816(float* c, const uint32_t* a, const uint32_t* b) {
    asm volatile("mma.sync.aligned.m16n8k16.row.col.f32.bf16.bf16.f32 "
                 "{%0,%1,%2,%3}, {%4,%5,%6,%7}, {%8,%9}, {%0,%1,%2,%3};"
                 : "+f"(c[0]), "+f"(c[1]), "+f"(c[2]), "+f"(c[3])
                 : "r"(a[0]), "r"(a[1]), "r"(a[2]), "r"(a[3]), "r"(b[0]), "r"(b[1]));
}
__device__ __forceinline__ void mma16816h(float* c, const uint32_t* a, const uint32_t* b) {
    asm volatile("mma.sync.aligned.m16n8k16.row.col.f32.f16.f16.f32 "
                 "{%0,%1,%2,%3}, {%4,%5,%6,%7}, {%8,%9}, {%0,%1,%2,%3};"
                 : "+f"(c[0]), "+f"(c[1]), "+f"(c[2]), "+f"(c[3])
                 : "r"(a[0]), "r"(a[1]), "r"(a[2]), "r"(a[3]), "r"(b[0]), "r"(b[1]));
}

// ---------------- CSR row_ptr from sorted edge_dst ----------------
__global__ void build_row_ptr_kernel(const int* __restrict__ dst, int n_edges) {
    int i = blockIdx.x * blockDim.x + threadIdx.x;
    if (i > N_NODES) return;
    int lo = 0, hi = n_edges;
    while (lo < hi) {
        int mid = (lo + hi) >> 1;
        if (dst[mid] < i) lo = mid + 1; else hi = mid;
    }
    g_row_ptr[i] = lo;
}

// ---------------- weight prep: transpose + splits ----------------
__device__ __forceinline__ void split_store(__nv_bfloat16* ph, __nv_bfloat16* pl, float v) {
    __nv_bfloat16 hi = __float2bfloat16(v);
    *ph = hi;
    *pl = __float2bfloat16(v - __bfloat162float(hi));
}
__global__ void prep_w_kernel(const float* __restrict__ W1, const float* __restrict__ W2,
                              const float* __restrict__ WL1, const float* __restrict__ WL2,
                              const float* __restrict__ bL1, const float* __restrict__ bL2) {
    int i = blockIdx.x * blockDim.x + threadIdx.x;
    if (i < KDIM * NHID) {
        int n = i >> 8, k = i & 255;
        split_store(&g_w1t_h[i], &g_w1t_l[i], W1[k * NHID + n]);
        split_store(&g_w2t_h[i], &g_w2t_l[i], W2[k * NHID + n]);
    }
    if (i < 128 * KDIM) {
        int n = i >> 8, k = i & 255;
        float v = (n < NCLASS) ? WL1[k * NCLASS + n] : WL2[k * NCLASS + (n - NCLASS)];
        __half hi = __float2half_rn(v);
        g_whH[i] = hi;
        g_whL[i] = __float2half_rn(v - __half2float(hi));
    }
    if (i < 2 * NCLASS)
        g_headb[i] = (i < NCLASS) ? bL1[i] : bL2[i - NCLASS];
}

// ---------------- x -> bf16 hi/lo (vectorized: 4 floats/thread) ----------------
struct __align__(8) bf16x4v { __nv_bfloat162 a, b; };
__global__ void convert_x_kernel(const float4* __restrict__ x4) {
    int i = blockIdx.x * blockDim.x + threadIdx.x;
    if (i >= N_NODES * NFEAT / 4) return;
    float4 v = x4[i];
    __nv_bfloat16 h0 = __float2bfloat16(v.x), h1 = __float2bfloat16(v.y);
    __nv_bfloat16 h2 = __float2bfloat16(v.z), h3 = __float2bfloat16(v.w);
    bf16x4v hv; hv.a = __nv_bfloat162(h0, h1); hv.b = __nv_bfloat162(h2, h3);
    *(bf16x4v*)(g_xh + (size_t)i * 4) = hv;
    bf16x4v lv;
    lv.a = __nv_bfloat162(__float2bfloat16(v.x - __bfloat162float(h0)),
                          __float2bfloat16(v.y - __bfloat162float(h1)));
    lv.b = __nv_bfloat162(__float2bfloat16(v.z - __bfloat162float(h2)),
                          __float2bfloat16(v.w - __bfloat162float(h3)));
    *(bf16x4v*)(g_xl + (size_t)i * 4) = lv;
}

// ---------------- mma.sync split-bf16 GEMM (CTA 128x128, KC=32, 2 CTA/SM) ----------------
constexpr int KC     = 32;
constexpr int ROWB   = 80;             // (32+8) halves * 2B; 8-row ldsm conflict-free
constexpr int TILEB  = 128 * ROWB;     // 10240
constexpr int STAGEB = 4 * TILEB;      // 40960  (tiles: Ah, Al, Bh, Bl)
constexpr int GEMM_SMEM = 2 * STAGEB;  // 81920  (2 CTAs/SM)

__global__ void __launch_bounds__(256, 2) gemm_mma_kernel(
    const __nv_bfloat16* __restrict__ Ah, const __nv_bfloat16* __restrict__ Al,
    const __nv_bfloat16* __restrict__ Bh, const __nv_bfloat16* __restrict__ Bl,
    __half* __restrict__ out, int M)
{
    extern __shared__ __align__(128) char smem[];
    const int tid = threadIdx.x, lane = tid & 31, wid = tid >> 5;
    const int wm = wid >> 2, wn = wid & 3;            // 2(M) x 4(N) warps, warp tile 64x32
    const int m0 = blockIdx.y * 128;
    const int n0 = blockIdx.x * 128;
    const __nv_bfloat16* BhO = Bh + (size_t)n0 * KDIM;
    const __nv_bfloat16* BlO = Bl + (size_t)n0 * KDIM;
    uint32_t sb = (uint32_t)__cvta_generic_to_shared(smem);

    float acc[4][4][4];
#pragma unroll
    for (int a = 0; a < 4; a++)
#pragma unroll
        for (int b = 0; b < 4; b++)
#pragma unroll
            for (int c = 0; c < 4; c++) acc[a][b][c] = 0.f;

    auto load_stage = [&](int stage, int kc) {
        uint32_t base = sb + stage * STAGEB;
        for (int i = tid; i < 2048; i += 256) {
            int t = i >> 9, rc = i & 511, r = rc >> 2, ch = rc & 3;
            const __nv_bfloat16* src;
            bool v = true;
            if (t == 0)      { src = Ah  + (size_t)(m0 + r) * KDIM + kc + ch * 8; v = (m0 + r) < M; }
            else if (t == 1) { src = Al  + (size_t)(m0 + r) * KDIM + kc + ch * 8; v = (m0 + r) < M; }
            else if (t == 2) { src = BhO + (size_t)r * KDIM + kc + ch * 8; }
            else             { src = BlO + (size_t)r * KDIM + kc + ch * 8; }
            cp16(base + t * TILEB + r * ROWB + ch * 16, src, v);
        }
    };

    const int ar  = lane & 15;
    const int acx = ((lane >> 4) & 1) * 8;
    const int br  = ((lane >> 4) << 3) + (lane & 7);
    const int bc  = ((lane >> 3) & 1) * 8;

    auto compute = [&](int stage) {
        uint32_t aH = sb + stage * STAGEB;
        uint32_t aL = aH + TILEB;
        uint32_t bH = aH + 2 * TILEB;
        uint32_t bL = aH + 3 * TILEB;
#pragma unroll
        for (int k16 = 0; k16 < KC / 16; k16++) {
            uint32_t ah[4][4], al[4][4], bh[4][2], bl[4][2];
#pragma unroll
            for (int mf = 0; mf < 4; mf++) {
                uint32_t off = (uint32_t)((wm * 64 + mf * 16 + ar) * ROWB + (acx + k16 * 16) * 2);
                ldsm4(ah[mf], aH + off);
                ldsm4(al[mf], aL + off);
            }
#pragma unroll
            for (int np = 0; np < 2; np++) {
                uint32_t off = (uint32_t)((wn * 32 + np * 16 + br) * ROWB + (bc + k16 * 16) * 2);
                uint32_t t[4];
                ldsm4(t, bH + off);
                bh[np*2][0] = t[0]; bh[np*2][1] = t[1]; bh[np*2+1][0] = t[2]; bh[np*2+1][1] = t[3];
                ldsm4(t, bL + off);
                bl[np*2][0] = t[0]; bl[np*2][1] = t[1]; bl[np*2+1][0] = t[2]; bl[np*2+1][1] = t[3];
            }
#pragma unroll
            for (int mf = 0; mf < 4; mf++)
#pragma unroll
                for (int nf = 0; nf < 4; nf++) {
                    mma16816(acc[mf][nf], ah[mf], bh[nf]);
                    mma16816(acc[mf][nf], ah[mf], bl[nf]);
                    mma16816(acc[mf][nf], al[mf], bh[nf]);
                }
        }
    };

    constexpr int NIT = KDIM / KC;   // 8
    load_stage(0, 0);
    CP_COMMIT();
#pragma unroll
    for (int it = 0; it < NIT; it++) {
        if (it + 1 < NIT) {
            load_stage((it + 1) & 1, (it + 1) * KC);
            CP_COMMIT();
            asm volatile("cp.async.wait_group 1;" ::: "memory");
        } else {
            asm volatile("cp.async.wait_group 0;" ::: "memory");
        }
        __syncthreads();
        compute(it & 1);
        __syncthreads();
    }

    // epilogue: fp16 S
#pragma unroll
    for (int mf = 0; mf < 4; mf++) {
        int rbase = m0 + wm * 64 + mf * 16 + (lane >> 2);
#pragma unroll
        for (int nf = 0; nf < 4; nf++) {
            int col = n0 + wn * 32 + nf * 8 + (lane & 3) * 2;
#pragma unroll
            for (int h = 0; h < 2; h++) {
                int row = rbase + h * 8;
                if (row >= M) continue;
                *(__half2*)(out + (size_t)row * NHID + col) =
                    __floats2half2_rn(acc[mf][nf][h * 2], acc[mf][nf][h * 2 + 1]);
            }
        }
    }
}

// ---------------- head GEMM: fp16 2-term (A=h2 fp16, B=WL^T fp16 hi/lo) ----------------
constexpr int HSTAGEB  = 3 * TILEB;     // 30720  (tiles: A, Bh, Bl)
constexpr int HEAD_SMEM = 2 * HSTAGEB;  // 61440

__global__ void __launch_bounds__(256, 2) head_gemm_kernel(
    const __half* __restrict__ A, const __half* __restrict__ Bh, const __half* __restrict__ Bl,
    float* __restrict__ out, int M)
{
    extern __shared__ __align__(128) char smem[];
    const int tid = threadIdx.x, lane = tid & 31, wid = tid >> 5;
    const int wm = wid >> 2, wn = wid & 3;
    const int m0 = blockIdx.x * 128;
    uint32_t sb = (uint32_t)__cvta_generic_to_shared(smem);

    float acc[4][4][4];
#pragma unroll
    for (int a = 0; a < 4; a++)
#pragma unroll
        for (int b = 0; b < 4; b++)
#pragma unroll
            for (int c = 0; c < 4; c++) acc[a][b][c] = 0.f;

    auto load_stage = [&](int stage, int kc) {
        uint32_t base = sb + stage * HSTAGEB;
        for (int i = tid; i < 1536; i += 256) {
            int t = i / 512, rc = i & 511, r = rc >> 2, ch = rc & 3;
            const __half* src;
            bool v = true;
            if (t == 0)      { src = A  + (size_t)(m0 + r) * KDIM + kc + ch * 8; v = (m0 + r) < M; }
            else if (t == 1) { src = Bh + (size_t)r * KDIM + kc + ch * 8; }
            else             { src = Bl + (size_t)r * KDIM + kc + ch * 8; }
            cp16(base + t * TILEB + r * ROWB + ch * 16, src, v);
        }
    };

    const int ar  = lane & 15;
    const int acx = ((lane >> 4) & 1) * 8;
    const int br  = ((lane >> 4) << 3) + (lane & 7);
    const int bc  = ((lane >> 3) & 1) * 8;

    auto compute = [&](int stage) {
        uint32_t aT = sb + stage * HSTAGEB;
        uint32_t bH = aT + TILEB;
        uint32_t bL = aT + 2 * TILEB;
#pragma unroll
        for (int k16 = 0; k16 < KC / 16; k16++) {
            uint32_t ah[4][4], bh[4][2], bl[4][2];
#pragma unroll
            for (int mf = 0; mf < 4; mf++) {
                uint32_t off = (uint32_t)((wm * 64 + mf * 16 + ar) * ROWB + (acx + k16 * 16) * 2);
                ldsm4(ah[mf], aT + off);
            }
#pragma unroll
            for (int np = 0; np < 2; np++) {
                uint32_t off = (uint32_t)((wn * 32 + np * 16 + br) * ROWB + (bc + k16 * 16) * 2);
                uint32_t t[4];
                ldsm4(t, bH + off);
                bh[np*2][0] = t[0]; bh[np*2][1] = t[1]; bh[np*2+1][0] = t[2]; bh[np*2+1][1] = t[3];
                ldsm4(t, bL + off);
                bl[np*2][0] = t[0]; bl[np*2][1] = t[1]; bl[np*2+1][0] = t[2]; bl[np*2+1][1] = t[3];
            }
#pragma unroll
            for (int mf = 0; mf < 4; mf++)
#pragma unroll
                for (int nf = 0; nf < 4; nf++) {
                    mma16816h(acc[mf][nf], ah[mf], bh[nf]);
                    mma16816h(acc[mf][nf], ah[mf], bl[nf]);
                }
        }
    };

    constexpr int NIT = KDIM / KC;   // 8
    load_stage(0, 0);
    CP_COMMIT();
#pragma unroll
    for (int it = 0; it < NIT; it++) {
        if (it + 1 < NIT) {
            load_stage((it + 1) & 1, (it + 1) * KC);
            CP_COMMIT();
            asm volatile("cp.async.wait_group 1;" ::: "memory");
        } else {
            asm volatile("cp.async.wait_group 0;" ::: "memory");
        }
        __syncthreads();
        compute(it & 1);
        __syncthreads();
    }

    // epilogue: bias + split twin-head store (fp32)
#pragma unroll
    for (int mf = 0; mf < 4; mf++) {
        int rbase = m0 + wm * 64 + mf * 16 + (lane >> 2);
#pragma unroll
        for (int nf = 0; nf < 4; nf++) {
            int col = wn * 32 + nf * 8 + (lane & 3) * 2;
#pragma unroll
            for (int h = 0; h < 2; h++) {
                int row = rbase + h * 8;
                if (row >= M) continue;
                float2 v = make_float2(acc[mf][nf][h * 2] + g_headb[col],
                                       acc[mf][nf][h * 2 + 1] + g_headb[col + 1]);
                float* dst = (col < NCLASS)
                    ? out + (size_t)row * NCLASS + col
                    : out + (size_t)N_NODES * NCLASS + (size_t)row * NCLASS + (col - NCLASS);
                *(float2*)dst = v;
            }
        }
    }
}

// ---------------- SpMM (fp16 gather, 256 cols, one pass) + bias + relu ----------------
// SPLIT=true: emit bf16 hi/lo (feeds next GEMM). SPLIT=false: emit fp16 (feeds head).
struct __align__(8) bf16x4 { __nv_bfloat162 a, b; };
__device__ __forceinline__ void emit4(__nv_bfloat16* Hh, __nv_bfloat16* Hl, size_t idx,
                                      const float* v) {
    __nv_bfloat16 h0 = __float2bfloat16(v[0]), h1 = __float2bfloat16(v[1]);
    __nv_bfloat16 h2 = __float2bfloat16(v[2]), h3 = __float2bfloat16(v[3]);
    bf16x4 hv; hv.a = __nv_bfloat162(h0, h1); hv.b = __nv_bfloat162(h2, h3);
    *(bf16x4*)(Hh + idx) = hv;
    bf16x4 lv;
    lv.a = __nv_bfloat162(__float2bfloat16(v[0] - __bfloat162float(h0)),
                          __float2bfloat16(v[1] - __bfloat162float(h1)));
    lv.b = __nv_bfloat162(__float2bfloat16(v[2] - __bfloat162float(h2)),
                          __float2bfloat16(v[3] - __bfloat162float(h3)));
    *(bf16x4*)(Hl + idx) = lv;
}

__device__ __forceinline__ void acc_edge(float* acc, float w, const uint4& q) {
    const __half2* hp = (const __half2*)&q;
#pragma unroll
    for (int j = 0; j < 4; j++) {
        float2 f = __half22float2(hp[j]);
        acc[2 * j] += w * f.x;
        acc[2 * j + 1] += w * f.y;
    }
}

template <bool SPLIT>
__global__ void __launch_bounds__(256) spmm_relu_kernel(
    const __half* __restrict__ S, const int* __restrict__ src,
    const float* __restrict__ w, const float* __restrict__ bias,
    void* __restrict__ out_a, void* __restrict__ out_b)
{
    int node = (blockIdx.x * blockDim.x + threadIdx.x) >> 5;
    if (node >= N_NODES) return;
    int lane = threadIdx.x & 31;
    int e0 = g_row_ptr[node], e1 = g_row_ptr[node + 1];
    const __half* Sc = S + lane * 8;   // 8 fp16 cols per lane = 16B

    float acc[8];
#pragma unroll
    for (int j = 0; j < 8; j++) acc[j] = 0.f;

    int e = e0;
    for (; e + 4 <= e1; e += 4) {
        int   s0 = __ldg(src + e),     s1 = __ldg(src + e + 1);
        int   s2 = __ldg(src + e + 2), s3 = __ldg(src + e + 3);
        float w0 = __ldg(w + e),     w1 = __ldg(w + e + 1);
        float w2 = __ldg(w + e + 2), w3 = __ldg(w + e + 3);
        uint4 q0 = __ldg((const uint4*)(Sc + (size_t)s0 * NHID));
        uint4 q1 = __ldg((const uint4*)(Sc + (size_t)s1 * NHID));
        uint4 q2 = __ldg((const uint4*)(Sc + (size_t)s2 * NHID));
        uint4 q3 = __ldg((const uint4*)(Sc + (size_t)s3 * NHID));
        acc_edge(acc, w0, q0); acc_edge(acc, w1, q1);
        acc_edge(acc, w2, q2); acc_edge(acc, w3, q3);
    }
    for (; e < e1; e++) {
        int   s  = __ldg(src + e);
        float sw = __ldg(w + e);
        uint4 q = __ldg((const uint4*)(Sc + (size_t)s * NHID));
        acc_edge(acc, sw, q);
    }

    float4 b0 = *(const float4*)(bias + lane * 8);
    float4 b1 = *(const float4*)(bias + lane * 8 + 4);
    float v[8];
    v[0] = fmaxf(acc[0] + b0.x, 0.f); v[1] = fmaxf(acc[1] + b0.y, 0.f);
    v[2] = fmaxf(acc[2] + b0.z, 0.f); v[3] = fmaxf(acc[3] + b0.w, 0.f);
    v[4] = fmaxf(acc[4] + b1.x, 0.f); v[5] = fmaxf(acc[5] + b1.y, 0.f);
    v[6] = fmaxf(acc[6] + b1.z, 0.f); v[7] = fmaxf(acc[7] + b1.w, 0.f);

    size_t idx = (size_t)node * NHID + lane * 8;
    if (SPLIT) {
        emit4((__nv_bfloat16*)out_a, (__nv_bfloat16*)out_b, idx, v);
        emit4((__nv_bfloat16*)out_a, (__nv_bfloat16*)out_b, idx + 4, v + 4);
    } else {
        __half2 p[4];
        p[0] = __floats2half2_rn(v[0], v[1]); p[1] = __floats2half2_rn(v[2], v[3]);
        p[2] = __floats2half2_rn(v[4], v[5]); p[3] = __floats2half2_rn(v[6], v[7]);
        *(uint4*)((__half*)out_a + idx) = *(uint4*)p;
    }
}

// ---------------- launch ----------------
extern "C" void kernel_launch(void* const* d_in, const int* in_sizes, int n_in,
                              void* d_out, int out_size) {
    const float* x   = (const float*)d_in[0];
    const int*   es  = (const int*)  d_in[1];
    const int*   ed  = (const int*)  d_in[2];
    const float* ew  = (const float*)d_in[3];
    const float* W1  = (const float*)d_in[4];
    const float* b1  = (const float*)d_in[5];
    const float* W2  = (const float*)d_in[6];
    const float* b2  = (const float*)d_in[7];
    const float* WL1 = (const float*)d_in[8];
    const float* bL1 = (const float*)d_in[9];
    const float* WL2 = (const float*)d_in[10];
    const float* bL2 = (const float*)d_in[11];
    int n_edges = in_sizes[1];

    __half *S, *h16, *whH, *whL;
    __nv_bfloat16 *xh, *xl, *hh, *hl, *w1h, *w1l, *w2h, *w2l;
    cudaGetSymbolAddress((void**)&S,   g_S16);
    cudaGetSymbolAddress((void**)&h16, g_h16);
    cudaGetSymbolAddress((void**)&whH, g_whH);   cudaGetSymbolAddress((void**)&whL, g_whL);
    cudaGetSymbolAddress((void**)&xh,  g_xh);    cudaGetSymbolAddress((void**)&xl,  g_xl);
    cudaGetSymbolAddress((void**)&hh,  g_hh);    cudaGetSymbolAddress((void**)&hl,  g_hl);
    cudaGetSymbolAddress((void**)&w1h, g_w1t_h); cudaGetSymbolAddress((void**)&w1l, g_w1t_l);
    cudaGetSymbolAddress((void**)&w2h, g_w2t_h); cudaGetSymbolAddress((void**)&w2l, g_w2t_l);

    cudaFuncSetAttribute(gemm_mma_kernel,
                         cudaFuncAttributeMaxDynamicSharedMemorySize, GEMM_SMEM);
    cudaFuncSetAttribute(head_gemm_kernel,
                         cudaFuncAttributeMaxDynamicSharedMemorySize, HEAD_SMEM);

    const int MTILES = (N_NODES + 127) / 128;   // 782
    const int spmm_blocks = (N_NODES + 7) / 8;  // 8 warps/block

    build_row_ptr_kernel<<<(N_NODES + 256) / 256, 256>>>(ed, n_edges);
    prep_w_kernel<<<(KDIM * NHID + 255) / 256, 256>>>(W1, W2, WL1, WL2, bL1, bL2);
    convert_x_kernel<<<(N_NODES * NFEAT / 4 + 255) / 256, 256>>>((const float4*)x);

    // layer 1
    gemm_mma_kernel<<<dim3(2, MTILES), 256, GEMM_SMEM>>>(xh, xl, w1h, w1l, S, N_NODES);
    spmm_relu_kernel<true><<<spmm_blocks, 256>>>(S, es, ew, b1, hh, hl);
    // layer 2
    gemm_mma_kernel<<<dim3(2, MTILES), 256, GEMM_SMEM>>>(hh, hl, w2h, w2l, S, N_NODES);
    spmm_relu_kernel<false><<<spmm_blocks, 256>>>(S, es, ew, b2, h16, nullptr);
    // twin heads (fp16 2-term)
    head_gemm_kernel<<<MTILES, 256, HEAD_SMEM>>>(h16, whH, whL, (float*)d_out, N_NODES);
}

// round 17
// speedup vs baseline: 3.3502x; 1.1445x over previous
#include <cuda_runtime.h>
#include <cuda_bf16.h>
#include <cuda_fp16.h>
#include <cstdint>

#define N_NODES 100000
#define NFEAT   256
#define NHID    256
#define NCLASS  64
#define KDIM    256

// ---------------- scratch (device globals; no runtime allocation) ----------------
__device__ __align__(128) __half g_S16[(size_t)N_NODES * NHID];   // GEMM out / SpMM in
__device__ __align__(128) __half g_A16[(size_t)N_NODES * NHID];   // SpMM out / GEMM A in (also x16)
__device__ __align__(128) __half g_w1H[KDIM * NHID], g_w1L[KDIM * NHID];  // W1^T fp16 hi/lo [N,K]
__device__ __align__(128) __half g_w2H[KDIM * NHID], g_w2L[KDIM * NHID];  // W2^T
__device__ __align__(128) __half g_whH[128 * KDIM],  g_whL[128 * KDIM];   // [WL1|WL2]^T
__device__ float g_headb[2 * NCLASS];
__device__ int   g_row_ptr[N_NODES + 1];

// ---------------- small PTX helpers ----------------
__device__ __forceinline__ void cp16(uint32_t s, const void* g, bool v) {
    int sz = v ? 16 : 0;
    asm volatile("cp.async.cg.shared.global [%0], [%1], 16, %2;"
                 :: "r"(s), "l"(__cvta_generic_to_global(g)), "r"(sz));
}
#define CP_COMMIT() asm volatile("cp.async.commit_group;" ::: "memory")

__device__ __forceinline__ void ldsm4(uint32_t* r, uint32_t a) {
    asm volatile("ldmatrix.sync.aligned.m8n8.x4.shared.b16 {%0,%1,%2,%3}, [%4];"
                 : "=r"(r[0]), "=r"(r[1]), "=r"(r[2]), "=r"(r[3]) : "r"(a));
}
__device__ __forceinline__ void mma16816h(float* c, const uint32_t* a, const uint32_t* b) {
    asm volatile("mma.sync.aligned.m16n8k16.row.col.f32.f16.f16.f32 "
                 "{%0,%1,%2,%3}, {%4,%5,%6,%7}, {%8,%9}, {%0,%1,%2,%3};"
                 : "+f"(c[0]), "+f"(c[1]), "+f"(c[2]), "+f"(c[3])
                 : "r"(a[0]), "r"(a[1]), "r"(a[2]), "r"(a[3]), "r"(b[0]), "r"(b[1]));
}

// ---------------- CSR row_ptr from sorted edge_dst ----------------
__global__ void build_row_ptr_kernel(const int* __restrict__ dst, int n_edges) {
    int i = blockIdx.x * blockDim.x + threadIdx.x;
    if (i > N_NODES) return;
    int lo = 0, hi = n_edges;
    while (lo < hi) {
        int mid = (lo + hi) >> 1;
        if (dst[mid] < i) lo = mid + 1; else hi = mid;
    }
    g_row_ptr[i] = lo;
}

// ---------------- weight prep: transpose + fp16 hi/lo split ----------------
__device__ __forceinline__ void hsplit(__half* ph, __half* pl, float v) {
    __half hi = __float2half_rn(v);
    *ph = hi;
    *pl = __float2half_rn(v - __half2float(hi));
}
__global__ void prep_w_kernel(const float* __restrict__ W1, const float* __restrict__ W2,
                              const float* __restrict__ WL1, const float* __restrict__ WL2,
                              const float* __restrict__ bL1, const float* __restrict__ bL2) {
    int i = blockIdx.x * blockDim.x + threadIdx.x;
    if (i < KDIM * NHID) {
        int n = i >> 8, k = i & 255;
        hsplit(&g_w1H[i], &g_w1L[i], W1[k * NHID + n]);
        hsplit(&g_w2H[i], &g_w2L[i], W2[k * NHID + n]);
    }
    if (i < 128 * KDIM) {
        int n = i >> 8, k = i & 255;
        float v = (n < NCLASS) ? WL1[k * NCLASS + n] : WL2[k * NCLASS + (n - NCLASS)];
        hsplit(&g_whH[i], &g_whL[i], v);
    }
    if (i < 2 * NCLASS)
        g_headb[i] = (i < NCLASS) ? bL1[i] : bL2[i - NCLASS];
}

// ---------------- x -> fp16 (vectorized: 4 floats/thread) ----------------
__global__ void convert_x_kernel(const float4* __restrict__ x4) {
    int i = blockIdx.x * blockDim.x + threadIdx.x;
    if (i >= N_NODES * NFEAT / 4) return;
    float4 v = x4[i];
    __half2 p[2];
    p[0] = __floats2half2_rn(v.x, v.y);
    p[1] = __floats2half2_rn(v.z, v.w);
    *(uint2*)(g_A16 + (size_t)i * 4) = *(uint2*)p;
}

// ---------------- fp16 2-term GEMM (CTA 128x128, KC=32, 2 CTA/SM) ----------------
// C = A @ (Bh+Bl)^T, fp32 accum. A: [M,256] fp16; B: [Nrows,256] fp16 hi/lo (W^T).
// !HEAD: out = fp16 S (256-col). HEAD: out = fp32 logits, bias + twin-head split cols.
constexpr int KC     = 32;
constexpr int ROWB   = 80;             // (32+8) halves * 2B; 8-row ldsm conflict-free
constexpr int TILEB  = 128 * ROWB;     // 10240
constexpr int STAGEB = 3 * TILEB;      // 30720  (tiles: A, Bh, Bl)
constexpr int GEMM_SMEM = 2 * STAGEB;  // 61440  (2 CTAs/SM)

template <bool HEAD>
__global__ void __launch_bounds__(256, 2) gemm_fp16_kernel(
    const __half* __restrict__ A, const __half* __restrict__ Bh, const __half* __restrict__ Bl,
    void* __restrict__ out_v, int M)
{
    extern __shared__ __align__(128) char smem[];
    const int tid = threadIdx.x, lane = tid & 31, wid = tid >> 5;
    const int wm = wid >> 2, wn = wid & 3;            // 2(M) x 4(N) warps, warp tile 64x32
    const int m0 = blockIdx.y * 128;
    const int n0 = blockIdx.x * 128;
    const __half* BhO = Bh + (size_t)n0 * KDIM;
    const __half* BlO = Bl + (size_t)n0 * KDIM;
    uint32_t sb = (uint32_t)__cvta_generic_to_shared(smem);

    float acc[4][4][4];
#pragma unroll
    for (int a = 0; a < 4; a++)
#pragma unroll
        for (int b = 0; b < 4; b++)
#pragma unroll
            for (int c = 0; c < 4; c++) acc[a][b][c] = 0.f;

    // stage loader: 3 tiles x 128 rows x 4 chunks(16B) = 1536 cp.async
    auto load_stage = [&](int stage, int kc) {
        uint32_t base = sb + stage * STAGEB;
        for (int i = tid; i < 1536; i += 256) {
            int t = i / 512, rc = i & 511, r = rc >> 2, ch = rc & 3;
            const __half* src;
            bool v = true;
            if (t == 0)      { src = A   + (size_t)(m0 + r) * KDIM + kc + ch * 8; v = (m0 + r) < M; }
            else if (t == 1) { src = BhO + (size_t)r * KDIM + kc + ch * 8; }
            else             { src = BlO + (size_t)r * KDIM + kc + ch * 8; }
            cp16(base + t * TILEB + r * ROWB + ch * 16, src, v);
        }
    };

    const int ar  = lane & 15;
    const int acx = ((lane >> 4) & 1) * 8;
    const int br  = ((lane >> 4) << 3) + (lane & 7);
    const int bc  = ((lane >> 3) & 1) * 8;

    auto compute = [&](int stage) {
        uint32_t aT = sb + stage * STAGEB;
        uint32_t bH = aT + TILEB;
        uint32_t bL = aT + 2 * TILEB;
#pragma unroll
        for (int k16 = 0; k16 < KC / 16; k16++) {
            uint32_t ah[4][4], bh[4][2], bl[4][2];
#pragma unroll
            for (int mf = 0; mf < 4; mf++) {
                uint32_t off = (uint32_t)((wm * 64 + mf * 16 + ar) * ROWB + (acx + k16 * 16) * 2);
                ldsm4(ah[mf], aT + off);
            }
#pragma unroll
            for (int np = 0; np < 2; np++) {
                uint32_t off = (uint32_t)((wn * 32 + np * 16 + br) * ROWB + (bc + k16 * 16) * 2);
                uint32_t t[4];
                ldsm4(t, bH + off);
                bh[np*2][0] = t[0]; bh[np*2][1] = t[1]; bh[np*2+1][0] = t[2]; bh[np*2+1][1] = t[3];
                ldsm4(t, bL + off);
                bl[np*2][0] = t[0]; bl[np*2][1] = t[1]; bl[np*2+1][0] = t[2]; bl[np*2+1][1] = t[3];
            }
#pragma unroll
            for (int mf = 0; mf < 4; mf++)
#pragma unroll
                for (int nf = 0; nf < 4; nf++) {
                    mma16816h(acc[mf][nf], ah[mf], bh[nf]);
                    mma16816h(acc[mf][nf], ah[mf], bl[nf]);
                }
        }
    };

    constexpr int NIT = KDIM / KC;   // 8
    load_stage(0, 0);
    CP_COMMIT();
#pragma unroll
    for (int it = 0; it < NIT; it++) {
        if (it + 1 < NIT) {
            load_stage((it + 1) & 1, (it + 1) * KC);
            CP_COMMIT();
            asm volatile("cp.async.wait_group 1;" ::: "memory");
        } else {
            asm volatile("cp.async.wait_group 0;" ::: "memory");
        }
        __syncthreads();
        compute(it & 1);
        __syncthreads();
    }

    // ---- epilogue ----
#pragma unroll
    for (int mf = 0; mf < 4; mf++) {
        int rbase = m0 + wm * 64 + mf * 16 + (lane >> 2);
#pragma unroll
        for (int nf = 0; nf < 4; nf++) {
            int col = (HEAD ? 0 : n0) + wn * 32 + nf * 8 + (lane & 3) * 2;
#pragma unroll
            for (int h = 0; h < 2; h++) {
                int row = rbase + h * 8;
                if (row >= M) continue;
                float2 v = make_float2(acc[mf][nf][h * 2], acc[mf][nf][h * 2 + 1]);
                if (!HEAD) {
                    __half* o = (__half*)out_v;
                    *(__half2*)(o + (size_t)row * NHID + col) = __floats2half2_rn(v.x, v.y);
                } else {
                    float* o = (float*)out_v;
                    v.x += g_headb[col]; v.y += g_headb[col + 1];
                    float* dst = (col < NCLASS)
                        ? o + (size_t)row * NCLASS + col
                        : o + (size_t)N_NODES * NCLASS + (size_t)row * NCLASS + (col - NCLASS);
                    *(float2*)dst = v;
                }
            }
        }
    }
}

// ---------------- SpMM (fp16 gather, 256 cols, one pass) + bias + relu -> fp16 ----------------
// Working set = 51MB -> L2-resident; one LDG.128 per edge per lane.
__device__ __forceinline__ void acc_edge(float* acc, float w, const uint4& q) {
    const __half2* hp = (const __half2*)&q;
#pragma unroll
    for (int j = 0; j < 4; j++) {
        float2 f = __half22float2(hp[j]);
        acc[2 * j] += w * f.x;
        acc[2 * j + 1] += w * f.y;
    }
}

__global__ void __launch_bounds__(256) spmm_relu_kernel(
    const __half* __restrict__ S, const int* __restrict__ src,
    const float* __restrict__ w, const float* __restrict__ bias,
    __half* __restrict__ H)
{
    int node = (blockIdx.x * blockDim.x + threadIdx.x) >> 5;
    if (node >= N_NODES) return;
    int lane = threadIdx.x & 31;
    int e0 = g_row_ptr[node], e1 = g_row_ptr[node + 1];
    const __half* Sc = S + lane * 8;   // 8 fp16 cols per lane = 16B

    float acc[8];
#pragma unroll
    for (int j = 0; j < 8; j++) acc[j] = 0.f;

    int e = e0;
    for (; e + 4 <= e1; e += 4) {
        int   s0 = __ldg(src + e),     s1 = __ldg(src + e + 1);
        int   s2 = __ldg(src + e + 2), s3 = __ldg(src + e + 3);
        float w0 = __ldg(w + e),     w1 = __ldg(w + e + 1);
        float w2 = __ldg(w + e + 2), w3 = __ldg(w + e + 3);
        uint4 q0 = __ldg((const uint4*)(Sc + (size_t)s0 * NHID));
        uint4 q1 = __ldg((const uint4*)(Sc + (size_t)s1 * NHID));
        uint4 q2 = __ldg((const uint4*)(Sc + (size_t)s2 * NHID));
        uint4 q3 = __ldg((const uint4*)(Sc + (size_t)s3 * NHID));
        acc_edge(acc, w0, q0); acc_edge(acc, w1, q1);
        acc_edge(acc, w2, q2); acc_edge(acc, w3, q3);
    }
    for (; e < e1; e++) {
        int   s  = __ldg(src + e);
        float sw = __ldg(w + e);
        uint4 q = __ldg((const uint4*)(Sc + (size_t)s * NHID));
        acc_edge(acc, sw, q);
    }

    float4 b0 = *(const float4*)(bias + lane * 8);
    float4 b1 = *(const float4*)(bias + lane * 8 + 4);
    __half2 p[4];
    p[0] = __floats2half2_rn(fmaxf(acc[0] + b0.x, 0.f), fmaxf(acc[1] + b0.y, 0.f));
    p[1] = __floats2half2_rn(fmaxf(acc[2] + b0.z, 0.f), fmaxf(acc[3] + b0.w, 0.f));
    p[2] = __floats2half2_rn(fmaxf(acc[4] + b1.x, 0.f), fmaxf(acc[5] + b1.y, 0.f));
    p[3] = __floats2half2_rn(fmaxf(acc[6] + b1.z, 0.f), fmaxf(acc[7] + b1.w, 0.f));
    *(uint4*)(H + (size_t)node * NHID + lane * 8) = *(uint4*)p;
}

// ---------------- launch ----------------
extern "C" void kernel_launch(void* const* d_in, const int* in_sizes, int n_in,
                              void* d_out, int out_size) {
    const float* x   = (const float*)d_in[0];
    const int*   es  = (const int*)  d_in[1];
    const int*   ed  = (const int*)  d_in[2];
    const float* ew  = (const float*)d_in[3];
    const float* W1  = (const float*)d_in[4];
    const float* b1  = (const float*)d_in[5];
    const float* W2  = (const float*)d_in[6];
    const float* b2  = (const float*)d_in[7];
    const float* WL1 = (const float*)d_in[8];
    const float* bL1 = (const float*)d_in[9];
    const float* WL2 = (const float*)d_in[10];
    const float* bL2 = (const float*)d_in[11];
    int n_edges = in_sizes[1];

    __half *S, *A, *w1H, *w1L, *w2H, *w2L, *whH, *whL;
    cudaGetSymbolAddress((void**)&S,   g_S16);
    cudaGetSymbolAddress((void**)&A,   g_A16);
    cudaGetSymbolAddress((void**)&w1H, g_w1H); cudaGetSymbolAddress((void**)&w1L, g_w1L);
    cudaGetSymbolAddress((void**)&w2H, g_w2H); cudaGetSymbolAddress((void**)&w2L, g_w2L);
    cudaGetSymbolAddress((void**)&whH, g_whH); cudaGetSymbolAddress((void**)&whL, g_whL);

    cudaFuncSetAttribute(gemm_fp16_kernel<false>,
                         cudaFuncAttributeMaxDynamicSharedMemorySize, GEMM_SMEM);
    cudaFuncSetAttribute(gemm_fp16_kernel<true>,
                         cudaFuncAttributeMaxDynamicSharedMemorySize, GEMM_SMEM);

    const int MTILES = (N_NODES + 127) / 128;   // 782
    const int spmm_blocks = (N_NODES + 7) / 8;  // 8 warps/block

    build_row_ptr_kernel<<<(N_NODES + 256) / 256, 256>>>(ed, n_edges);
    prep_w_kernel<<<(KDIM * NHID + 255) / 256, 256>>>(W1, W2, WL1, WL2, bL1, bL2);
    convert_x_kernel<<<(N_NODES * NFEAT / 4 + 255) / 256, 256>>>((const float4*)x);

    // layer 1
    gemm_fp16_kernel<false><<<dim3(2, MTILES), 256, GEMM_SMEM>>>(A, w1H, w1L, S, N_NODES);
    spmm_relu_kernel<<<spmm_blocks, 256>>>(S, es, ew, b1, A);
    // layer 2
    gemm_fp16_kernel<false><<<dim3(2, MTILES), 256, GEMM_SMEM>>>(A, w2H, w2L, S, N_NODES);
    spmm_relu_kernel<<<spmm_blocks, 256>>>(S, es, ew, b2, A);
    // twin heads (fp16 2-term)
    gemm_fp16_kernel<true><<<dim3(1, MTILES), 256, GEMM_SMEM>>>(A, whH, whL, (float*)d_out, N_NODES);
}